// round 6
// baseline (speedup 1.0000x reference)
#include <cuda_runtime.h>
#include <cstdint>

#define B 8
#define DIM 192
#define Hh 128
#define Ww 128
#define KS 7
#define PAD 3
#define HID 48
#define KK 49          // 7*7
#define PLANE (Hh*Ww)  // 16384
#define OUTW (DIM*KK)  // 9408
#define EPS 1e-5f

typedef unsigned long long ull;

// -------- scratch (device globals; no allocation allowed) --------
__device__ float g_pooled[B * DIM];
// channel-pair-interleaved dynamic weights:
// float index  b*OUTW + (c>>1)*98 + k*2 + (c&1)
// i.e. float2 index  pp*49 + k   for global plane-pair pp = (b*DIM+c)/2
__device__ __align__(16) float g_wdyn[B * OUTW];

// -------- f32x2 packed helpers --------
__device__ __forceinline__ ull ffma2(ull a, ull b, ull c) {
    ull d;
    asm("fma.rn.f32x2 %0, %1, %2, %3;" : "=l"(d) : "l"(a), "l"(b), "l"(c));
    return d;
}
__device__ __forceinline__ ull pk2(float lo, float hi) {
    ull r;
    asm("mov.b64 %0, {%1, %2};" : "=l"(r) : "f"(lo), "f"(hi));
    return r;
}
__device__ __forceinline__ void unpk2(ull v, float& lo, float& hi) {
    asm("mov.b64 {%0, %1}, %2;" : "=f"(lo), "=f"(hi) : "l"(v));
}

// ============================================================
// Kernel 1: global average pool over HxW per (b,c) plane
// ============================================================
__global__ __launch_bounds__(256) void pool_kernel(const float* __restrict__ x) {
    int bc = blockIdx.x;
    const float4* p = reinterpret_cast<const float4*>(x + (size_t)bc * PLANE);
    float s = 0.f;
    #pragma unroll 8
    for (int i = threadIdx.x; i < PLANE / 4; i += 256) {
        float4 v = p[i];
        s += (v.x + v.y) + (v.z + v.w);
    }
    #pragma unroll
    for (int off = 16; off > 0; off >>= 1)
        s += __shfl_down_sync(0xffffffffu, s, off);
    __shared__ float red[8];
    int lane = threadIdx.x & 31, warp = threadIdx.x >> 5;
    if (lane == 0) red[warp] = s;
    __syncthreads();
    if (warp == 0) {
        float t = (lane < 8) ? red[lane] : 0.f;
        #pragma unroll
        for (int off = 4; off > 0; off >>= 1)
            t += __shfl_down_sync(0xffffffffu, t, off);
        if (lane == 0) g_pooled[bc] = t * (1.0f / (float)PLANE);
    }
}

// ============================================================
// Kernel 2 (fused): y = relu(BN(pooled @ w1^T)) per block, then
// wdyn chunk; stores CHANNEL-PAIR-INTERLEAVED for the conv kernel.
// ============================================================
#define W2_CHUNK 128
__global__ __launch_bounds__(128) void gen_wdyn_kernel(
    const float* __restrict__ w1,
    const float* __restrict__ gamma, const float* __restrict__ beta,
    const float* __restrict__ mean,  const float* __restrict__ var,
    const float* __restrict__ w2, const float* __restrict__ b2) {
    int b = blockIdx.y;
    int obase = blockIdx.x * W2_CHUNK;
    int t = threadIdx.x;

    __shared__ float sy[HID];
    __shared__ float w2s[W2_CHUNK * (HID + 1)];

    if (t < HID) {
        const float* pr = g_pooled + b * DIM;
        const float* wr = w1 + t * DIM;
        float s = 0.f;
        #pragma unroll 8
        for (int c = 0; c < DIM; c++) s = fmaf(pr[c], wr[c], s);
        s = (s - mean[t]) * rsqrtf(var[t] + EPS) * gamma[t] + beta[t];
        sy[t] = s > 0.f ? s : 0.f;
    }

    const int n_f4 = W2_CHUNK * HID / 4;
    const float4* w2v = reinterpret_cast<const float4*>(w2 + (size_t)obase * HID);
    int max_f4 = (OUTW - obase) * HID / 4;
    for (int i = t; i < n_f4; i += 128) {
        float4 v = (i < max_f4) ? w2v[i] : make_float4(0.f, 0.f, 0.f, 0.f);
        int row = i / (HID / 4);
        int col = (i % (HID / 4)) * 4;
        float* dst = &w2s[row * (HID + 1) + col];
        dst[0] = v.x; dst[1] = v.y; dst[2] = v.z; dst[3] = v.w;
    }
    __syncthreads();

    int o = obase + t;
    if (o < OUTW) {
        float acc = b2[o];
        const float* wr = &w2s[t * (HID + 1)];
        #pragma unroll
        for (int h = 0; h < HID; h++) acc = fmaf(sy[h], wr[h], acc);
        int c = o / KK, k = o - c * KK;
        g_wdyn[(size_t)b * OUTW + (size_t)(c >> 1) * (2 * KK) + k * 2 + (c & 1)] = acc;
    }
}

// ============================================================
// Kernel 3: depthwise 7x7 conv + bias, f32x2 over a CHANNEL PAIR.
// block = 256 thr = 32 colgroups x 8 rowgroups; covers 2 planes x
// 32-row strip x 128 cols; each thread: 4x4 spatial patch x 2 ch.
// Two kh-passes keep packed weights in registers under the 128-reg
// budget (launch_bounds(256,2) -> 2 blocks/SM, 16 warps).
// All FFMA2 operands are natural pairs: tile is channel-interleaved
// float2 (window = 5x LDS.128/row), weights pre-interleaved (LDS.64).
// ============================================================
#define STRIP 32
#define TROWS (STRIP + KS - 1)   // 38
#define TCOLS (Ww + KS - 1)      // 134
#define TS2 136                  // float2 row stride (1088 B, 16B-aligned)

__global__ __launch_bounds__(256, 2) void dwconv2_kernel(
    const float* __restrict__ x, const float* __restrict__ bias,
    float* __restrict__ out) {
    int pp = blockIdx.x;            // plane pair: planes 2pp, 2pp+1
    int strip = blockIdx.y;
    int pc = pp * 2;
    int c0 = pc % DIM;
    int r0 = strip * STRIP;

    __shared__ __align__(16) float2 tile[TROWS * TS2];
    __shared__ __align__(16) float2 wsm[KK];

    int tid = threadIdx.x;

    if (tid < KK)
        wsm[tid] = reinterpret_cast<const float2*>(g_wdyn)[(size_t)pp * KK + tid];

    // channel-interleaved halo tile
    const float* p0 = x + (size_t)pc * PLANE;
    const float* p1 = p0 + PLANE;
    for (int idx = tid; idx < TROWS * TCOLS; idx += 256) {
        int rr = idx / TCOLS, cc = idx % TCOLS;
        int gr = r0 + rr - PAD, gc = cc - PAD;
        float v0 = 0.f, v1 = 0.f;
        if (gr >= 0 && gr < Hh && gc >= 0 && gc < Ww) {
            int o = gr * Ww + gc;
            v0 = __ldg(p0 + o); v1 = __ldg(p1 + o);
        }
        tile[rr * TS2 + cc] = make_float2(v0, v1);
    }
    __syncthreads();

    int cg = tid & 31, rg = tid >> 5;
    int col = cg * 4;                // float2 column
    int rbase = rg * 4;

    ull binit = pk2(bias[c0], bias[c0 + 1]);
    ull acc[4][4];
    #pragma unroll
    for (int i = 0; i < 4; i++)
        #pragma unroll
        for (int j = 0; j < 4; j++) acc[i][j] = binit;

    const ull* wp = reinterpret_cast<const ull*>(wsm);

    // ---- pass A: kh 0..3 (28 weight pairs in regs), tile rows 0..6 ----
    {
        ull wA[28];
        #pragma unroll
        for (int i = 0; i < 28; i++) wA[i] = wp[i];
        #pragma unroll
        for (int ir = 0; ir < 7; ir++) {
            const ulonglong2* tr = reinterpret_cast<const ulonglong2*>(
                &tile[(rbase + ir) * TS2 + col]);
            ull vv[10];
            #pragma unroll
            for (int q = 0; q < 5; q++) {
                ulonglong2 u = tr[q];
                vv[2 * q] = u.x; vv[2 * q + 1] = u.y;
            }
            #pragma unroll
            for (int kh = 0; kh < 4; kh++) {
                int orr = ir - kh;
                if (orr >= 0 && orr < 4) {
                    #pragma unroll
                    for (int j = 0; j < 4; j++) {
                        ull a = acc[orr][j];
                        #pragma unroll
                        for (int kw = 0; kw < KS; kw++)
                            a = ffma2(vv[j + kw], wA[kh * KS + kw], a);
                        acc[orr][j] = a;
                    }
                }
            }
        }
    }

    // ---- pass B: kh 4..6 (21 weight pairs in regs), tile rows 4..9 ----
    {
        ull wB[21];
        #pragma unroll
        for (int i = 0; i < 21; i++) wB[i] = wp[28 + i];
        #pragma unroll
        for (int ir = 4; ir < 10; ir++) {
            const ulonglong2* tr = reinterpret_cast<const ulonglong2*>(
                &tile[(rbase + ir) * TS2 + col]);
            ull vv[10];
            #pragma unroll
            for (int q = 0; q < 5; q++) {
                ulonglong2 u = tr[q];
                vv[2 * q] = u.x; vv[2 * q + 1] = u.y;
            }
            #pragma unroll
            for (int kh = 4; kh < 7; kh++) {
                int orr = ir - kh;
                if (orr >= 0 && orr < 4) {
                    #pragma unroll
                    for (int j = 0; j < 4; j++) {
                        ull a = acc[orr][j];
                        #pragma unroll
                        for (int kw = 0; kw < KS; kw++)
                            a = ffma2(vv[j + kw], wB[(kh - 4) * KS + kw], a);
                        acc[orr][j] = a;
                    }
                }
            }
        }
    }

    // store: de-interleave pairs into the two channel planes
    float* o0 = out + (size_t)pc * PLANE + (size_t)(r0 + rbase) * Ww + col;
    #pragma unroll
    for (int orr = 0; orr < 4; orr++) {
        float l0, h0, l1, h1, l2, h2, l3, h3;
        unpk2(acc[orr][0], l0, h0);
        unpk2(acc[orr][1], l1, h1);
        unpk2(acc[orr][2], l2, h2);
        unpk2(acc[orr][3], l3, h3);
        *reinterpret_cast<float4*>(o0 + (size_t)orr * Ww) =
            make_float4(l0, l1, l2, l3);
        *reinterpret_cast<float4*>(o0 + PLANE + (size_t)orr * Ww) =
            make_float4(h0, h1, h2, h3);
    }
}

// ============================================================
// launch
// inputs: 0:x 1:w1 2:bn_gamma 3:bn_beta 4:bn_mean 5:bn_var 6:w2 7:b2 8:bias
// ============================================================
extern "C" void kernel_launch(void* const* d_in, const int* in_sizes, int n_in,
                              void* d_out, int out_size) {
    const float* x     = (const float*)d_in[0];
    const float* w1    = (const float*)d_in[1];
    const float* gamma = (const float*)d_in[2];
    const float* beta  = (const float*)d_in[3];
    const float* mean  = (const float*)d_in[4];
    const float* var   = (const float*)d_in[5];
    const float* w2    = (const float*)d_in[6];
    const float* b2    = (const float*)d_in[7];
    const float* bias  = (const float*)d_in[8];
    float* out = (float*)d_out;

    pool_kernel<<<B * DIM, 256>>>(x);
    dim3 g2((OUTW + W2_CHUNK - 1) / W2_CHUNK, B);
    gen_wdyn_kernel<<<g2, 128>>>(w1, gamma, beta, mean, var, w2, b2);
    dim3 g3(B * DIM / 2, Hh / STRIP);
    dwconv2_kernel<<<g3, 256>>>(x, bias, out);
}

// round 8
// speedup vs baseline: 1.2820x; 1.2820x over previous
#include <cuda_runtime.h>
#include <cstdint>

#define B 8
#define DIM 192
#define Hh 128
#define Ww 128
#define KS 7
#define PAD 3
#define HID 48
#define KK 49          // 7*7
#define PLANE (Hh*Ww)  // 16384
#define OUTW (DIM*KK)  // 9408
#define EPS 1e-5f

// -------- scratch (device globals; no allocation allowed) --------
__device__ float g_pooled[B * DIM];      // [b, c]
__device__ float g_wdyn[B * OUTW];       // [b, c*49 + k]

// ============================================================
// Kernel 1: global average pool; 2 planes per block for MLP.
// grid = B*DIM/2, 256 threads.
// ============================================================
__global__ __launch_bounds__(256) void pool_kernel(const float* __restrict__ x) {
    int p0 = blockIdx.x * 2;
    const float4* a = reinterpret_cast<const float4*>(x + (size_t)p0 * PLANE);
    const float4* b = a + PLANE / 4;
    float s0 = 0.f, s1 = 0.f, s2 = 0.f, s3 = 0.f;
    #pragma unroll 8
    for (int i = threadIdx.x; i < PLANE / 4; i += 256) {
        float4 va = a[i];
        float4 vb = b[i];
        s0 += va.x + va.y; s1 += va.z + va.w;
        s2 += vb.x + vb.y; s3 += vb.z + vb.w;
    }
    float sa = s0 + s1, sb = s2 + s3;
    #pragma unroll
    for (int off = 16; off > 0; off >>= 1) {
        sa += __shfl_down_sync(0xffffffffu, sa, off);
        sb += __shfl_down_sync(0xffffffffu, sb, off);
    }
    __shared__ float red[16];
    int lane = threadIdx.x & 31, warp = threadIdx.x >> 5;
    if (lane == 0) { red[warp] = sa; red[8 + warp] = sb; }
    __syncthreads();
    if (warp == 0) {
        float t = (lane < 16) ? red[lane] : 0.f;
        #pragma unroll
        for (int off = 4; off > 0; off >>= 1)
            t += __shfl_down_sync(0xffffffffu, t, off);
        if (lane < 16 && (lane & 7) == 0)          // lanes 0 and 8 ONLY
            g_pooled[p0 + (lane >> 3)] = t * (1.0f / (float)PLANE);
    }
}

// ============================================================
// Kernel 2 (fused): y = relu(BN(pooled @ w1^T)) per block, then
// wdyn[b, o] = y . w2[o,:] + b2[o] for a 128-wide chunk of o.
// grid = (74, B), 128 threads.
// ============================================================
#define W2_CHUNK 128
__global__ __launch_bounds__(128) void gen_wdyn_kernel(
    const float* __restrict__ w1,
    const float* __restrict__ gamma, const float* __restrict__ beta,
    const float* __restrict__ mean,  const float* __restrict__ var,
    const float* __restrict__ w2, const float* __restrict__ b2) {
    int b = blockIdx.y;
    int obase = blockIdx.x * W2_CHUNK;
    int t = threadIdx.x;

    __shared__ float sy[HID];
    __shared__ float w2s[W2_CHUNK * (HID + 1)];

    if (t < HID) {
        const float* pr = g_pooled + b * DIM;
        const float* wr = w1 + t * DIM;
        float s = 0.f;
        #pragma unroll 8
        for (int c = 0; c < DIM; c++) s = fmaf(pr[c], wr[c], s);
        s = (s - mean[t]) * rsqrtf(var[t] + EPS) * gamma[t] + beta[t];
        sy[t] = s > 0.f ? s : 0.f;
    }

    const int n_f4 = W2_CHUNK * HID / 4;
    const float4* w2v = reinterpret_cast<const float4*>(w2 + (size_t)obase * HID);
    int max_f4 = (OUTW - obase) * HID / 4;
    for (int i = t; i < n_f4; i += 128) {
        float4 v = (i < max_f4) ? w2v[i] : make_float4(0.f, 0.f, 0.f, 0.f);
        int row = i / (HID / 4);
        int col = (i % (HID / 4)) * 4;
        float* dst = &w2s[row * (HID + 1) + col];
        dst[0] = v.x; dst[1] = v.y; dst[2] = v.z; dst[3] = v.w;
    }
    __syncthreads();

    int o = obase + t;
    if (o < OUTW) {
        float acc = b2[o];
        const float* wr = &w2s[t * (HID + 1)];
        #pragma unroll
        for (int h = 0; h < HID; h++) acc = fmaf(sy[h], wr[h], acc);
        g_wdyn[(size_t)b * OUTW + o] = acc;
    }
}

// ============================================================
// Kernel 3: per-sample depthwise 7x7 conv + bias.
// grid = (B*DIM, 2): one plane x one 64-row strip per block.
// 256 threads = 32 col-groups x 8 row-groups; each thread computes
// a 4-col x 8-row patch (32 outputs, 1568 FFMA, 45 vector LDS).
// 49 weights live in registers (launch_bounds(256,2) -> 128-reg budget).
// Tile 70 x 134 (stride 136, 16B-aligned window loads), ~38 KB smem.
// ============================================================
#define STRIP 64
#define TROWS (STRIP + KS - 1)   // 70
#define TCOLS (Ww + KS - 1)      // 134
#define TSTRIDE 136              // 544 B row stride, keeps 16B alignment
#define RPT 8                    // output rows per thread

__global__ __launch_bounds__(256, 2) void dwconv_kernel(
    const float* __restrict__ x, const float* __restrict__ bias,
    float* __restrict__ out) {
    int bc = blockIdx.x;             // b*DIM + c
    int strip = blockIdx.y;
    int r0 = strip * STRIP;

    __shared__ __align__(16) float tile[TROWS * TSTRIDE];
    __shared__ float wsh[KK];

    int tid = threadIdx.x;
    if (tid < KK) wsh[tid] = g_wdyn[(size_t)bc * KK + tid];

    // tile load: warp w handles rows w, w+8, ...; lanes stride cols
    const float* plane = x + (size_t)bc * PLANE;
    int warp = tid >> 5, lane = tid & 31;
    for (int rr = warp; rr < TROWS; rr += 8) {
        int gr = r0 + rr - PAD;
        bool rok = (gr >= 0) && (gr < Hh);
        const float* rp = plane + (size_t)gr * Ww;
        #pragma unroll
        for (int cc = lane; cc < TCOLS; cc += 32) {
            int gc = cc - PAD;
            float v = 0.f;
            if (rok && gc >= 0 && gc < Ww) v = __ldg(rp + gc);
            tile[rr * TSTRIDE + cc] = v;
        }
    }
    __syncthreads();

    // weights to registers
    float w[KK];
    #pragma unroll
    for (int k = 0; k < KK; k++) w[k] = wsh[k];

    int cg = tid & 31;               // col group (4 cols)
    int rg = tid >> 5;               // row group (8 rows)
    int col = cg * 4;
    int rbase = rg * RPT;

    float bia = bias[bc % DIM];
    float acc[RPT][4];
    #pragma unroll
    for (int i = 0; i < RPT; i++)
        #pragma unroll
        for (int j = 0; j < 4; j++) acc[i][j] = bia;

    #pragma unroll
    for (int ir = 0; ir < RPT + KS - 1; ir++) {     // 14 tile rows
        const float* tr = &tile[(rbase + ir) * TSTRIDE + col];
        float4 va = *reinterpret_cast<const float4*>(tr);
        float4 vb = *reinterpret_cast<const float4*>(tr + 4);
        float2 vc = *reinterpret_cast<const float2*>(tr + 8);
        float v[10] = {va.x, va.y, va.z, va.w, vb.x, vb.y, vb.z, vb.w, vc.x, vc.y};
        #pragma unroll
        for (int kh = 0; kh < KS; kh++) {
            int orr = ir - kh;
            if (orr >= 0 && orr < RPT) {
                #pragma unroll
                for (int j = 0; j < 4; j++) {
                    float s = acc[orr][j];
                    #pragma unroll
                    for (int kw = 0; kw < KS; kw++)
                        s = fmaf(v[j + kw], w[kh * KS + kw], s);
                    acc[orr][j] = s;
                }
            }
        }
    }

    float* op = out + (size_t)bc * PLANE + (size_t)(r0 + rbase) * Ww + col;
    #pragma unroll
    for (int orr = 0; orr < RPT; orr++)
        *reinterpret_cast<float4*>(op + (size_t)orr * Ww) =
            make_float4(acc[orr][0], acc[orr][1], acc[orr][2], acc[orr][3]);
}

// ============================================================
// launch
// inputs: 0:x 1:w1 2:bn_gamma 3:bn_beta 4:bn_mean 5:bn_var 6:w2 7:b2 8:bias
// ============================================================
extern "C" void kernel_launch(void* const* d_in, const int* in_sizes, int n_in,
                              void* d_out, int out_size) {
    const float* x     = (const float*)d_in[0];
    const float* w1    = (const float*)d_in[1];
    const float* gamma = (const float*)d_in[2];
    const float* beta  = (const float*)d_in[3];
    const float* mean  = (const float*)d_in[4];
    const float* var   = (const float*)d_in[5];
    const float* w2    = (const float*)d_in[6];
    const float* b2    = (const float*)d_in[7];
    const float* bias  = (const float*)d_in[8];
    float* out = (float*)d_out;

    pool_kernel<<<B * DIM / 2, 256>>>(x);
    dim3 g2((OUTW + W2_CHUNK - 1) / W2_CHUNK, B);
    gen_wdyn_kernel<<<g2, 128>>>(w1, gamma, beta, mean, var, w2, b2);
    dim3 g3(B * DIM, Hh / STRIP);
    dwconv_kernel<<<g3, 256>>>(x, bias, out);
}

// round 9
// speedup vs baseline: 1.7441x; 1.3605x over previous
#include <cuda_runtime.h>
#include <cstdint>

#define B 8
#define DIM 192
#define Hh 128
#define Ww 128
#define KS 7
#define PAD 3
#define HID 48
#define KK 49          // 7*7
#define PLANE (Hh*Ww)  // 16384
#define OUTW (DIM*KK)  // 9408
#define EPS 1e-5f

// -------- scratch (device globals; no allocation allowed) --------
__device__ float g_pooled[B * DIM];      // [b, c]
__device__ float g_wdyn[B * OUTW];       // [b, c*49 + k]

// -------- cp.async helpers --------
__device__ __forceinline__ void cp_async4(uint32_t saddr, const void* g, bool ok) {
    int sz = ok ? 4 : 0;
    asm volatile("cp.async.ca.shared.global [%0], [%1], 4, %2;"
                 :: "r"(saddr), "l"(g), "r"(sz));
}
__device__ __forceinline__ void cp_commit() {
    asm volatile("cp.async.commit_group;");
}
__device__ __forceinline__ void cp_wait_all() {
    asm volatile("cp.async.wait_group 0;");
}
__device__ __forceinline__ uint32_t smem_u32(const void* p) {
    return (uint32_t)__cvta_generic_to_shared(p);
}

// ============================================================
// Kernel 1: global average pool over HxW per (b,c) plane
// grid = B*DIM, 256 threads  (measured 18.9us, ~70% DRAM)
// ============================================================
__global__ __launch_bounds__(256) void pool_kernel(const float* __restrict__ x) {
    int bc = blockIdx.x;
    const float4* p = reinterpret_cast<const float4*>(x + (size_t)bc * PLANE);
    float s = 0.f;
    #pragma unroll 4
    for (int i = threadIdx.x; i < PLANE / 4; i += 256) {
        float4 v = p[i];
        s += (v.x + v.y) + (v.z + v.w);
    }
    #pragma unroll
    for (int off = 16; off > 0; off >>= 1)
        s += __shfl_down_sync(0xffffffffu, s, off);
    __shared__ float red[8];
    int lane = threadIdx.x & 31, warp = threadIdx.x >> 5;
    if (lane == 0) red[warp] = s;
    __syncthreads();
    if (warp == 0) {
        float t = (lane < 8) ? red[lane] : 0.f;
        #pragma unroll
        for (int off = 4; off > 0; off >>= 1)
            t += __shfl_down_sync(0xffffffffu, t, off);
        if (lane == 0) g_pooled[bc] = t * (1.0f / (float)PLANE);
    }
}

// ============================================================
// Kernel 2 (fused): y = relu(BN(pooled @ w1^T)) per block, then
// wdyn[b, o] = y . w2[o,:] + b2[o] for a 128-wide chunk of o.
// ============================================================
#define W2_CHUNK 128
__global__ __launch_bounds__(128) void gen_wdyn_kernel(
    const float* __restrict__ w1,
    const float* __restrict__ gamma, const float* __restrict__ beta,
    const float* __restrict__ mean,  const float* __restrict__ var,
    const float* __restrict__ w2, const float* __restrict__ b2) {
    int b = blockIdx.y;
    int obase = blockIdx.x * W2_CHUNK;
    int t = threadIdx.x;

    __shared__ float sy[HID];
    __shared__ float w2s[W2_CHUNK * (HID + 1)];

    if (t < HID) {
        const float* pr = g_pooled + b * DIM;
        const float* wr = w1 + t * DIM;
        float s = 0.f;
        #pragma unroll 8
        for (int c = 0; c < DIM; c++) s = fmaf(pr[c], wr[c], s);
        s = (s - mean[t]) * rsqrtf(var[t] + EPS) * gamma[t] + beta[t];
        sy[t] = s > 0.f ? s : 0.f;
    }

    const int n_f4 = W2_CHUNK * HID / 4;
    const float4* w2v = reinterpret_cast<const float4*>(w2 + (size_t)obase * HID);
    int max_f4 = (OUTW - obase) * HID / 4;
    for (int i = t; i < n_f4; i += 128) {
        float4 v = (i < max_f4) ? w2v[i] : make_float4(0.f, 0.f, 0.f, 0.f);
        int row = i / (HID / 4);
        int col = (i % (HID / 4)) * 4;
        float* dst = &w2s[row * (HID + 1) + col];
        dst[0] = v.x; dst[1] = v.y; dst[2] = v.z; dst[3] = v.w;
    }
    __syncthreads();

    int o = obase + t;
    if (o < OUTW) {
        float acc = b2[o];
        const float* wr = &w2s[t * (HID + 1)];
        #pragma unroll
        for (int h = 0; h < HID; h++) acc = fmaf(sy[h], wr[h], acc);
        g_wdyn[(size_t)b * OUTW + o] = acc;
    }
}

// ============================================================
// Kernel 3: persistent double-buffered depthwise 7x7 conv + bias.
// 304 blocks x 256 thr (2/SM), each loops over tiles
// (tile = one (b,c) plane x 32-row strip; 6144 tiles, 4 per plane).
// While computing tile t from smem buf[cur], cp.async streams tile
// t+grid into buf[cur^1] (tile data + its 49 weights). Compute body
// = R4's proven 4x4-patch / weights-in-registers loop.
// ============================================================
#define STRIP 32
#define TROWS (STRIP + KS - 1)   // 38
#define TCOLS (Ww + KS - 1)      // 134
#define TSTRIDE 136              // 544B row stride, 16B-aligned windows
#define NTILES (B * DIM * (Hh / STRIP))   // 6144
#define DW_GRID 304

__device__ __forceinline__ void load_tile_async(
    float* tbuf, float* wbuf, int tile, const float* __restrict__ x) {
    int bc = tile >> 2;
    int strip = tile & 3;
    int r0 = strip * STRIP;
    int tid = threadIdx.x, warp = tid >> 5, lane = tid & 31;

    if (tid < KK)
        cp_async4(smem_u32(wbuf + tid), &g_wdyn[(size_t)bc * KK + tid], true);

    const float* plane = x + (size_t)bc * PLANE;
    #pragma unroll
    for (int rr0 = 0; rr0 < TROWS + 7; rr0 += 8) {
        int rr = rr0 + warp;
        if (rr < TROWS) {
            int gr = r0 + rr - PAD;
            bool rok = (gr >= 0) && (gr < Hh);
            const float* rp = plane + (size_t)gr * Ww;
            #pragma unroll
            for (int cc = lane; cc < TCOLS; cc += 32) {
                int gc = cc - PAD;
                bool ok = rok && (gc >= 0) && (gc < Ww);
                cp_async4(smem_u32(tbuf + rr * TSTRIDE + cc),
                          ok ? (rp + gc) : plane, ok);
            }
        }
    }
}

__global__ __launch_bounds__(256, 2) void dwconv_kernel(
    const float* __restrict__ x, const float* __restrict__ bias,
    float* __restrict__ out) {
    __shared__ __align__(16) float tbuf[2][TROWS * TSTRIDE];
    __shared__ __align__(16) float wbuf[2][52];

    int tid = threadIdx.x;
    int cg = tid & 31, rg = tid >> 5;
    int col = cg * 4;
    int rbase = rg * 4;
    const int grid = gridDim.x;

    int t = blockIdx.x;
    if (t < NTILES) {
        load_tile_async(tbuf[0], wbuf[0], t, x);
        cp_commit();
    }
    int cur = 0;

    for (; t < NTILES; t += grid) {
        cp_wait_all();
        __syncthreads();

        int tn = t + grid;
        if (tn < NTILES) {
            load_tile_async(tbuf[cur ^ 1], wbuf[cur ^ 1], tn, x);
            cp_commit();
        }

        // ---- compute tile t from buf[cur] ----
        int bc = t >> 2;
        int r0 = (t & 3) * STRIP;

        // weights smem -> registers (13 vector LDS)
        float w[KK];
        {
            const float4* wv = reinterpret_cast<const float4*>(wbuf[cur]);
            #pragma unroll
            for (int q = 0; q < 12; q++) {
                float4 f = wv[q];
                w[4 * q + 0] = f.x; w[4 * q + 1] = f.y;
                w[4 * q + 2] = f.z; w[4 * q + 3] = f.w;
            }
            w[48] = wbuf[cur][48];
        }

        float bia = __ldg(&bias[bc % DIM]);
        float acc[4][4];
        #pragma unroll
        for (int i = 0; i < 4; i++)
            #pragma unroll
            for (int j = 0; j < 4; j++) acc[i][j] = bia;

        const float* tile = tbuf[cur];
        #pragma unroll
        for (int ir = 0; ir < 4 + KS - 1; ir++) {     // 10 tile rows
            const float* tr = &tile[(rbase + ir) * TSTRIDE + col];
            float4 va = *reinterpret_cast<const float4*>(tr);
            float4 vb = *reinterpret_cast<const float4*>(tr + 4);
            float2 vc = *reinterpret_cast<const float2*>(tr + 8);
            float v[10] = {va.x, va.y, va.z, va.w,
                           vb.x, vb.y, vb.z, vb.w, vc.x, vc.y};
            #pragma unroll
            for (int kh = 0; kh < KS; kh++) {
                int orr = ir - kh;
                if (orr >= 0 && orr < 4) {
                    #pragma unroll
                    for (int j = 0; j < 4; j++) {
                        float s = acc[orr][j];
                        #pragma unroll
                        for (int kw = 0; kw < KS; kw++)
                            s = fmaf(v[j + kw], w[kh * KS + kw], s);
                        acc[orr][j] = s;
                    }
                }
            }
        }

        float* op = out + (size_t)bc * PLANE + (size_t)(r0 + rbase) * Ww + col;
        #pragma unroll
        for (int orr = 0; orr < 4; orr++)
            *reinterpret_cast<float4*>(op + (size_t)orr * Ww) =
                make_float4(acc[orr][0], acc[orr][1], acc[orr][2], acc[orr][3]);

        cur ^= 1;
    }
}

// ============================================================
// launch
// inputs: 0:x 1:w1 2:bn_gamma 3:bn_beta 4:bn_mean 5:bn_var 6:w2 7:b2 8:bias
// ============================================================
extern "C" void kernel_launch(void* const* d_in, const int* in_sizes, int n_in,
                              void* d_out, int out_size) {
    const float* x     = (const float*)d_in[0];
    const float* w1    = (const float*)d_in[1];
    const float* gamma = (const float*)d_in[2];
    const float* beta  = (const float*)d_in[3];
    const float* mean  = (const float*)d_in[4];
    const float* var   = (const float*)d_in[5];
    const float* w2    = (const float*)d_in[6];
    const float* b2    = (const float*)d_in[7];
    const float* bias  = (const float*)d_in[8];
    float* out = (float*)d_out;

    pool_kernel<<<B * DIM, 256>>>(x);
    dim3 g2((OUTW + W2_CHUNK - 1) / W2_CHUNK, B);
    gen_wdyn_kernel<<<g2, 128>>>(w1, gamma, beta, mean, var, w2, b2);
    dwconv_kernel<<<DW_GRID, 256>>>(x, bias, out);
}

// round 10
// speedup vs baseline: 1.8782x; 1.0769x over previous
#include <cuda_runtime.h>
#include <cstdint>

#define B 8
#define DIM 192
#define Hh 128
#define Ww 128
#define KS 7
#define PAD 3
#define HID 48
#define KK 49          // 7*7
#define PLANE (Hh*Ww)  // 16384
#define OUTW (DIM*KK)  // 9408
#define EPS 1e-5f

// -------- scratch (device globals; no allocation allowed) --------
__device__ float g_pooled[B * DIM];      // [b, c]
__device__ float g_wdyn[B * OUTW];       // [b, c*49 + k]

// -------- cp.async helpers --------
__device__ __forceinline__ void cp_async4(uint32_t saddr, const void* g, bool ok) {
    int sz = ok ? 4 : 0;
    asm volatile("cp.async.ca.shared.global [%0], [%1], 4, %2;"
                 :: "r"(saddr), "l"(g), "r"(sz));
}
__device__ __forceinline__ void cp_async16(uint32_t saddr, const void* g, bool ok) {
    int sz = ok ? 16 : 0;
    asm volatile("cp.async.cg.shared.global [%0], [%1], 16, %2;"
                 :: "r"(saddr), "l"(g), "r"(sz));
}
__device__ __forceinline__ void cp_commit() {
    asm volatile("cp.async.commit_group;");
}
__device__ __forceinline__ void cp_wait_all() {
    asm volatile("cp.async.wait_group 0;");
}
__device__ __forceinline__ uint32_t smem_u32(const void* p) {
    return (uint32_t)__cvta_generic_to_shared(p);
}

// ============================================================
// Kernel 1: global average pool over HxW per (b,c) plane
// ============================================================
__global__ __launch_bounds__(256) void pool_kernel(const float* __restrict__ x) {
    int bc = blockIdx.x;
    const float4* p = reinterpret_cast<const float4*>(x + (size_t)bc * PLANE);
    float s = 0.f;
    #pragma unroll 4
    for (int i = threadIdx.x; i < PLANE / 4; i += 256) {
        float4 v = p[i];
        s += (v.x + v.y) + (v.z + v.w);
    }
    #pragma unroll
    for (int off = 16; off > 0; off >>= 1)
        s += __shfl_down_sync(0xffffffffu, s, off);
    __shared__ float red[8];
    int lane = threadIdx.x & 31, warp = threadIdx.x >> 5;
    if (lane == 0) red[warp] = s;
    __syncthreads();
    if (warp == 0) {
        float t = (lane < 8) ? red[lane] : 0.f;
        #pragma unroll
        for (int off = 4; off > 0; off >>= 1)
            t += __shfl_down_sync(0xffffffffu, t, off);
        if (lane == 0) g_pooled[bc] = t * (1.0f / (float)PLANE);
    }
}

// ============================================================
// Kernel 2 (fused): y = relu(BN(pooled @ w1^T)) per block, then
// wdyn[b, o] = y . w2[o,:] + b2[o] for a 128-wide chunk of o.
// ============================================================
#define W2_CHUNK 128
__global__ __launch_bounds__(128) void gen_wdyn_kernel(
    const float* __restrict__ w1,
    const float* __restrict__ gamma, const float* __restrict__ beta,
    const float* __restrict__ mean,  const float* __restrict__ var,
    const float* __restrict__ w2, const float* __restrict__ b2) {
    int b = blockIdx.y;
    int obase = blockIdx.x * W2_CHUNK;
    int t = threadIdx.x;

    __shared__ float sy[HID];
    __shared__ float w2s[W2_CHUNK * (HID + 1)];

    if (t < HID) {
        const float* pr = g_pooled + b * DIM;
        const float* wr = w1 + t * DIM;
        float s = 0.f;
        #pragma unroll 8
        for (int c = 0; c < DIM; c++) s = fmaf(pr[c], wr[c], s);
        s = (s - mean[t]) * rsqrtf(var[t] + EPS) * gamma[t] + beta[t];
        sy[t] = s > 0.f ? s : 0.f;
    }

    const int n_f4 = W2_CHUNK * HID / 4;
    const float4* w2v = reinterpret_cast<const float4*>(w2 + (size_t)obase * HID);
    int max_f4 = (OUTW - obase) * HID / 4;
    for (int i = t; i < n_f4; i += 128) {
        float4 v = (i < max_f4) ? w2v[i] : make_float4(0.f, 0.f, 0.f, 0.f);
        int row = i / (HID / 4);
        int col = (i % (HID / 4)) * 4;
        float* dst = &w2s[row * (HID + 1) + col];
        dst[0] = v.x; dst[1] = v.y; dst[2] = v.z; dst[3] = v.w;
    }
    __syncthreads();

    int o = obase + t;
    if (o < OUTW) {
        float acc = b2[o];
        const float* wr = &w2s[t * (HID + 1)];
        #pragma unroll
        for (int h = 0; h < HID; h++) acc = fmaf(sy[h], wr[h], acc);
        g_wdyn[(size_t)b * OUTW + o] = acc;
    }
}

// ============================================================
// Kernel 3: persistent double-buffered depthwise 7x7 conv + bias.
// Tile layout: gc=g lives at smem col g+4 (stride 136). Halo cols
// [0,4) and [132,136) are conv zero-padding -> zeroed ONCE at start,
// never rewritten. Per tile only the 128 main floats/row stream in
// as 32x 16B cp.async (zero-fill for OOB rows): 1216 chunks/tile,
// ~4.75 LDGSTS/thread (was 20).
// Window reads stay 16B-aligned by reading 12 floats (3x LDS.128)
// and using elements 1..10.
// ============================================================
#define STRIP 32
#define TROWS (STRIP + KS - 1)   // 38
#define TSTRIDE 136              // 544B row stride
#define COLOFF 4                 // smem col of gc=0
#define NTILES (B * DIM * (Hh / STRIP))   // 6144
#define DW_GRID 304
#define NCHUNK (TROWS * 32)      // 1216 16B chunks per tile

__device__ __forceinline__ void load_tile_async(
    float* tbuf, float* wbuf, int tile, const float* __restrict__ x) {
    int bc = tile >> 2;
    int strip = tile & 3;
    int r0 = strip * STRIP;
    int tid = threadIdx.x;

    if (tid < KK)
        cp_async4(smem_u32(wbuf + tid), &g_wdyn[(size_t)bc * KK + tid], true);

    const float* plane = x + (size_t)bc * PLANE;
    #pragma unroll
    for (int i = 0; i < 5; i++) {
        int idx = tid + i * 256;
        if (idx < NCHUNK) {
            int rr = idx >> 5;          // tile row
            int ch = idx & 31;          // 16B chunk within row
            int gr = r0 + rr - PAD;
            bool ok = (gr >= 0) && (gr < Hh);
            const float* src = ok ? (plane + (size_t)gr * Ww + ch * 4) : plane;
            cp_async16(smem_u32(tbuf + rr * TSTRIDE + COLOFF + ch * 4), src, ok);
        }
    }
}

__global__ __launch_bounds__(256, 2) void dwconv_kernel(
    const float* __restrict__ x, const float* __restrict__ bias,
    float* __restrict__ out) {
    __shared__ __align__(16) float tbuf[2][TROWS * TSTRIDE];
    __shared__ __align__(16) float wbuf[2][52];

    int tid = threadIdx.x;
    int cg = tid & 31, rg = tid >> 5;
    int col = cg * 4;
    int rbase = rg * 4;
    const int grid = gridDim.x;

    // zero the permanent halo columns of both buffers (done once)
    for (int i = tid; i < 2 * TROWS * 8; i += 256) {
        int bufi = i >= TROWS * 8;
        int j = i - bufi * TROWS * 8;
        int rr = j >> 3;
        int k = j & 7;                  // 0..3 -> left cols 0..3, 4..7 -> right
        int cc = (k < 4) ? k : (128 + COLOFF + (k - 4));
        tbuf[bufi][rr * TSTRIDE + cc] = 0.f;
    }

    int t = blockIdx.x;
    if (t < NTILES) {
        load_tile_async(tbuf[0], wbuf[0], t, x);
        cp_commit();
    }
    int cur = 0;

    for (; t < NTILES; t += grid) {
        cp_wait_all();
        __syncthreads();

        int tn = t + grid;
        if (tn < NTILES) {
            load_tile_async(tbuf[cur ^ 1], wbuf[cur ^ 1], tn, x);
            cp_commit();
        }

        // ---- compute tile t from buf[cur] ----
        int bc = t >> 2;
        int r0 = (t & 3) * STRIP;

        float w[KK];
        {
            const float4* wv = reinterpret_cast<const float4*>(wbuf[cur]);
            #pragma unroll
            for (int q = 0; q < 12; q++) {
                float4 f = wv[q];
                w[4 * q + 0] = f.x; w[4 * q + 1] = f.y;
                w[4 * q + 2] = f.z; w[4 * q + 3] = f.w;
            }
            w[48] = wbuf[cur][48];
        }

        float bia = __ldg(&bias[bc % DIM]);
        float acc[4][4];
        #pragma unroll
        for (int i = 0; i < 4; i++)
            #pragma unroll
            for (int j = 0; j < 4; j++) acc[i][j] = bia;

        const float* tile = tbuf[cur];
        #pragma unroll
        for (int ir = 0; ir < 4 + KS - 1; ir++) {     // 10 tile rows
            // window: 12 aligned floats starting at smem col `col`
            // (covers gc col-4 .. col+7; needed gc col-3 .. col+6 = v[1..10])
            const float* tr = &tile[(rbase + ir) * TSTRIDE + col];
            float4 A = *reinterpret_cast<const float4*>(tr);
            float4 Bv = *reinterpret_cast<const float4*>(tr + 4);
            float4 Cv = *reinterpret_cast<const float4*>(tr + 8);
            float v[12] = {A.x, A.y, A.z, A.w,
                           Bv.x, Bv.y, Bv.z, Bv.w,
                           Cv.x, Cv.y, Cv.z, Cv.w};
            #pragma unroll
            for (int kh = 0; kh < KS; kh++) {
                int orr = ir - kh;
                if (orr >= 0 && orr < 4) {
                    #pragma unroll
                    for (int jj = 0; jj < 4; jj++) {
                        float s = acc[orr][jj];
                        #pragma unroll
                        for (int kw = 0; kw < KS; kw++)
                            s = fmaf(v[jj + kw + 1], w[kh * KS + kw], s);
                        acc[orr][jj] = s;
                    }
                }
            }
        }

        float* op = out + (size_t)bc * PLANE + (size_t)(r0 + rbase) * Ww + col;
        #pragma unroll
        for (int orr = 0; orr < 4; orr++)
            *reinterpret_cast<float4*>(op + (size_t)orr * Ww) =
                make_float4(acc[orr][0], acc[orr][1], acc[orr][2], acc[orr][3]);

        cur ^= 1;
    }
}

// ============================================================
// launch
// inputs: 0:x 1:w1 2:bn_gamma 3:bn_beta 4:bn_mean 5:bn_var 6:w2 7:b2 8:bias
// ============================================================
extern "C" void kernel_launch(void* const* d_in, const int* in_sizes, int n_in,
                              void* d_out, int out_size) {
    const float* x     = (const float*)d_in[0];
    const float* w1    = (const float*)d_in[1];
    const float* gamma = (const float*)d_in[2];
    const float* beta  = (const float*)d_in[3];
    const float* mean  = (const float*)d_in[4];
    const float* var   = (const float*)d_in[5];
    const float* w2    = (const float*)d_in[6];
    const float* b2    = (const float*)d_in[7];
    const float* bias  = (const float*)d_in[8];
    float* out = (float*)d_out;

    pool_kernel<<<B * DIM, 256>>>(x);
    dim3 g2((OUTW + W2_CHUNK - 1) / W2_CHUNK, B);
    gen_wdyn_kernel<<<g2, 128>>>(w1, gamma, beta, mean, var, w2, b2);
    dwconv_kernel<<<DW_GRID, 256>>>(x, bias, out);
}